// round 7
// baseline (speedup 1.0000x reference)
#include <cuda_runtime.h>
#include <cuda_bf16.h>
#include <cstdint>

// ---------------- scratch (static __device__, no allocation) ----------------
#define MAXB 32
#define MAXN 500000
#define CAP  4096

__device__ float        g_pool8 [MAXB * 8 * 512];
__device__ float        g_queryT[512 * 32];              // [K-dim c][query b]
__device__ float        g_scores[(size_t)MAXB * MAXN];   // 64 MB
__device__ unsigned int g_rowmax[MAXB];
__device__ unsigned int g_hist16[MAXB * 16];
__device__ unsigned int g_thresh[MAXB];
__device__ int          g_ccount[MAXB];
__device__ unsigned int g_cu    [MAXB * CAP];
__device__ int          g_cidx  [MAXB * CAP];

__device__ __forceinline__ unsigned int fmono(float f) {
    unsigned int u = __float_as_uint(f);
    return (u & 0x80000000u) ? ~u : (u | 0x80000000u);
}
__device__ __forceinline__ float funmono(unsigned int u) {
    unsigned int o = (u & 0x80000000u) ? (u ^ 0x80000000u) : ~u;
    return __uint_as_float(o);
}

// packed fp32x2 FMA (FFMA2) — only reachable via PTX on sm_103a
__device__ __forceinline__ float2 ffma2(float2 a, float2 b, float2 c) {
    unsigned long long au = *reinterpret_cast<unsigned long long*>(&a);
    unsigned long long bu = *reinterpret_cast<unsigned long long*>(&b);
    unsigned long long cu = *reinterpret_cast<unsigned long long*>(&c);
    unsigned long long du;
    asm("fma.rn.f32x2 %0, %1, %2, %3;" : "=l"(du) : "l"(au), "l"(bu), "l"(cu));
    return *reinterpret_cast<float2*>(&du);
}

__device__ __forceinline__ void cp_async16(void* smem_dst, const void* gmem_src) {
    unsigned int d = (unsigned int)__cvta_generic_to_shared(smem_dst);
    asm volatile("cp.async.cg.shared.global [%0], [%1], 16;" :: "r"(d), "l"(gmem_src));
}

#define INV_SQRT_D 0.04419417382415922f   // 1/sqrt(512)

// ---------------- K0: zero small scratch ----------------
__global__ void k_zero() {
    int i = threadIdx.x;
    if (i < MAXB * 16) g_hist16[i] = 0u;
    if (i < MAXB) { g_ccount[i] = 0; g_rowmax[i] = 0u; }
}

// ---------------- K1: partial mean over T chunks ----------------
__global__ void k_mean(const float* __restrict__ hidden, int T) {
    int b  = blockIdx.x;
    int tc = blockIdx.y;              // 8 chunks
    int d  = threadIdx.x;             // 512 threads
    int rows_per = (T + 7) / 8;
    int t0 = tc * rows_per;
    int t1 = t0 + rows_per; if (t1 > T) t1 = T;
    const float* hp = hidden + ((size_t)b * T + t0) * 512 + d;
    float s0 = 0.f, s1 = 0.f, s2 = 0.f, s3 = 0.f;
    int nt = t1 - t0, t = 0;
    for (; t + 4 <= nt; t += 4) {
        s0 += hp[(size_t)(t + 0) * 512]; s1 += hp[(size_t)(t + 1) * 512];
        s2 += hp[(size_t)(t + 2) * 512]; s3 += hp[(size_t)(t + 3) * 512];
    }
    float s = (s0 + s1) + (s2 + s3);
    for (; t < nt; t++) s += hp[(size_t)t * 512];
    g_pool8[((size_t)b * 8 + tc) * 512 + d] = s;
}

// ---------------- K2: queryT[d][b] = (mean @ W + b)[d], high-MLP ----------------
__global__ void k_query(const float* __restrict__ W, const float* __restrict__ bias, int T) {
    __shared__ float p[512];
    int b = blockIdx.x, tid = threadIdx.x;          // 256 threads
    float invT = 1.0f / (float)T;
    for (int i = tid; i < 512; i += 256) {
        float s = 0.f;
#pragma unroll
        for (int tc = 0; tc < 8; tc++) s += g_pool8[((size_t)b * 8 + tc) * 512 + i];
        p[i] = s * invT;
    }
    __syncthreads();
    int d = tid * 2;
    float a0 = 0.f, a1 = 0.f;
#pragma unroll 16
    for (int k = 0; k < 512; k++) {
        float2 wv = *reinterpret_cast<const float2*>(W + (size_t)k * 512 + d);
        float pv = p[k];
        a0 += pv * wv.x; a1 += pv * wv.y;
    }
    g_queryT[(size_t)d * 32 + b]       = a0 + bias[d];
    g_queryT[(size_t)(d + 1) * 32 + b] = a1 + bias[d + 1];
}

// ---------------- K3: scores GEMM, query-paired FFMA2 + cp.async pipeline ----------------
// Block tile: 512 keys x 32 queries, K-chunk 8, double-buffered.
// 256 threads = 8 warps: qg = w&1 (16-query half), kg = w>>1 (128-key quarter).
// Thread: 4 keys x 16 queries (8 query-pair float2 accs per key).
#define TN 512
#define KC 8
__global__ __launch_bounds__(256, 2) void k_scores(const float* __restrict__ keys, int N) {
    __shared__ float4 ks4[2][2][TN];    // [buf][kp][row]   32 KB
    __shared__ float4 qt4[2][KC][8];    // [buf][c][j4]      2 KB
    int n0   = blockIdx.x * TN;
    int tid  = threadIdx.x;
    int lane = tid & 31;
    int w    = tid >> 5;
    int qg   = w & 1;
    int kg   = w >> 1;
    int krow = kg * 128 + lane;

    float2 acc[4][8];
#pragma unroll
    for (int i = 0; i < 4; i++)
#pragma unroll
        for (int j = 0; j < 8; j++) acc[i][j] = make_float2(0.f, 0.f);

    // ---- prefetch chunk 0 ----
    {
        int c0 = 0;
#pragma unroll
        for (int it = 0; it < 4; it++) {
            int v = it * 256 + tid;      // 0..1023 = 512 rows x 2 float4
            int row = v >> 1, c4 = v & 1;
            int n = n0 + row; if (n >= N) n = N - 1;
            cp_async16(&ks4[0][c4][row], keys + (size_t)n * 512 + c0 + c4 * 4);
        }
        if (tid < 64) {                  // KC x 8 = 64 float4s (FIX: was tid<128 -> smem OOB)
            int cl = tid >> 3, j4 = tid & 7;
            cp_async16(&qt4[0][cl][j4], g_queryT + (size_t)(c0 + cl) * 32 + j4 * 4);
        }
        asm volatile("cp.async.commit_group;");
    }

    const int NCH = 512 / KC;   // 64
    for (int ch = 0; ch < NCH; ch++) {
        int buf = ch & 1;
        if (ch + 1 < NCH) {
            int c0 = (ch + 1) * KC;
            int nb = (ch + 1) & 1;
#pragma unroll
            for (int it = 0; it < 4; it++) {
                int v = it * 256 + tid;
                int row = v >> 1, c4 = v & 1;
                int n = n0 + row; if (n >= N) n = N - 1;
                cp_async16(&ks4[nb][c4][row], keys + (size_t)n * 512 + c0 + c4 * 4);
            }
            if (tid < 64) {              // FIX: was tid<128
                int cl = tid >> 3, j4 = tid & 7;
                cp_async16(&qt4[nb][cl][j4], g_queryT + (size_t)(c0 + cl) * 32 + j4 * 4);
            }
            asm volatile("cp.async.commit_group;");
            asm volatile("cp.async.wait_group 1;");
        } else {
            asm volatile("cp.async.wait_group 0;");
        }
        __syncthreads();

#pragma unroll
        for (int kp = 0; kp < 2; kp++) {
            float4 kv[4];
#pragma unroll
            for (int i = 0; i < 4; i++) kv[i] = ks4[buf][kp][krow + 32 * i];
#pragma unroll
            for (int e = 0; e < 4; e++) {
                float4 qv[4];
#pragma unroll
                for (int j4 = 0; j4 < 4; j4++) qv[j4] = qt4[buf][kp * 4 + e][qg * 4 + j4];
#pragma unroll
                for (int i = 0; i < 4; i++) {
                    float ke = (e == 0) ? kv[i].x : (e == 1) ? kv[i].y
                             : (e == 2) ? kv[i].z : kv[i].w;
                    float2 kb = make_float2(ke, ke);
#pragma unroll
                    for (int j4 = 0; j4 < 4; j4++) {
                        acc[i][j4 * 2]     = ffma2(kb, make_float2(qv[j4].x, qv[j4].y), acc[i][j4 * 2]);
                        acc[i][j4 * 2 + 1] = ffma2(kb, make_float2(qv[j4].z, qv[j4].w), acc[i][j4 * 2 + 1]);
                    }
                }
            }
        }
        __syncthreads();
    }

    // epilogue: scores + per-row running max
#pragma unroll
    for (int j4 = 0; j4 < 4; j4++)
#pragma unroll
        for (int p = 0; p < 2; p++) {
            int m0 = qg * 16 + j4 * 4 + p * 2;
            unsigned int umx = 0u, umy = 0u;
#pragma unroll
            for (int i = 0; i < 4; i++) {
                int n = n0 + krow + 32 * i;
                if (n < N) {
                    float sx = acc[i][j4 * 2 + p].x * INV_SQRT_D;
                    float sy = acc[i][j4 * 2 + p].y * INV_SQRT_D;
                    g_scores[(size_t)m0 * N + n]       = sx;
                    g_scores[(size_t)(m0 + 1) * N + n] = sy;
                    unsigned int ux = fmono(sx), uy = fmono(sy);
                    if (ux > umx) umx = ux;
                    if (uy > umy) umy = uy;
                }
            }
            umx = __reduce_max_sync(0xffffffffu, umx);
            umy = __reduce_max_sync(0xffffffffu, umy);
            if (lane == 0) {
                atomicMax(&g_rowmax[m0], umx);
                atomicMax(&g_rowmax[m0 + 1], umy);
            }
        }
}

// ---------------- K4: 16-bin hist restricted to top bins below rowmax ----------------
#define F4PB 8192   // float4s per block
__global__ void k_hist(int N) {
    __shared__ unsigned int h[16];
    int row = blockIdx.y;
    int N4  = N >> 2;
    if (threadIdx.x < 16) h[threadIdx.x] = 0u;
    __syncthreads();
    int lo = (int)(g_rowmax[row] >> 20) - 15;
    const float4* sr = reinterpret_cast<const float4*>(g_scores + (size_t)row * N);
    int base = blockIdx.x * F4PB;
    for (int i = threadIdx.x; i < F4PB; i += 256) {
        int i4 = base + i;
        if (i4 < N4) {
            float4 v = sr[i4];
            int b0 = (int)(fmono(v.x) >> 20) - lo;
            int b1 = (int)(fmono(v.y) >> 20) - lo;
            int b2 = (int)(fmono(v.z) >> 20) - lo;
            int b3 = (int)(fmono(v.w) >> 20) - lo;
            if (b0 >= 0) atomicAdd(&h[b0], 1u);
            if (b1 >= 0) atomicAdd(&h[b1], 1u);
            if (b2 >= 0) atomicAdd(&h[b2], 1u);
            if (b3 >= 0) atomicAdd(&h[b3], 1u);
        }
    }
    if (blockIdx.x == 0) {
        for (int idx = N4 * 4 + (int)threadIdx.x; idx < N; idx += 256) {
            int b = (int)(fmono(g_scores[(size_t)row * N + idx]) >> 20) - lo;
            if (b >= 0) atomicAdd(&h[b], 1u);
        }
    }
    __syncthreads();
    if (threadIdx.x < 16 && h[threadIdx.x])
        atomicAdd(&g_hist16[row * 16 + threadIdx.x], h[threadIdx.x]);
}

// ---------------- K5: pick threshold bin (cum from top >= max_k) ----------------
__global__ void k_thresh(const int* __restrict__ pmk) {
    int row = blockIdx.x;
    if (threadIdx.x == 0) {
        int lo = (int)(g_rowmax[row] >> 20) - 15;
        int mk = *pmk; if (mk < 1) mk = 1; if (mk > CAP) mk = CAP;
        unsigned int cum = 0;
        int tb = lo;   // fallback: everything in range
        for (int b = 15; b >= 0; b--) {
            cum += g_hist16[row * 16 + b];
            if (cum >= (unsigned int)mk) { tb = lo + b; break; }
        }
        g_thresh[row] = (unsigned int)tb;
    }
}

// ---------------- K6: collect candidates with bin >= threshold ----------------
__global__ void k_collect(int N) {
    int row = blockIdx.y;
    int N4  = N >> 2;
    unsigned int tb = g_thresh[row];
    const float4* sr = reinterpret_cast<const float4*>(g_scores + (size_t)row * N);
    int base = blockIdx.x * F4PB;
    for (int i = threadIdx.x; i < F4PB; i += 256) {
        int i4 = base + i;
        if (i4 < N4) {
            float4 v = sr[i4];
            unsigned int u[4] = {fmono(v.x), fmono(v.y), fmono(v.z), fmono(v.w)};
#pragma unroll
            for (int e = 0; e < 4; e++) {
                if ((u[e] >> 20) >= tb) {
                    int pos = atomicAdd(&g_ccount[row], 1);
                    if (pos < CAP) {
                        g_cu  [row * CAP + pos] = u[e];
                        g_cidx[row * CAP + pos] = i4 * 4 + e;
                    }
                }
            }
        }
    }
    if (blockIdx.x == 0) {
        for (int idx = N4 * 4 + (int)threadIdx.x; idx < N; idx += 256) {
            unsigned int u = fmono(g_scores[(size_t)row * N + idx]);
            if ((u >> 20) >= tb) {
                int pos = atomicAdd(&g_ccount[row], 1);
                if (pos < CAP) {
                    g_cu  [row * CAP + pos] = u;
                    g_cidx[row * CAP + pos] = idx;
                }
            }
        }
    }
}

// ---------------- K7: exact rank, softmax(k_dyn), gather + aggregate ----------------
__global__ void k_final(const float* __restrict__ pool_params, const int* __restrict__ pkd,
                        float* __restrict__ out, int N) {
    __shared__ unsigned int cu[CAP];
    __shared__ int          ci[CAP];
    __shared__ float        selS[64];
    __shared__ int          selI[64];
    __shared__ float        w[64];
    int row = blockIdx.x;
    int c   = g_ccount[row]; if (c > CAP) c = CAP;
    for (int i = threadIdx.x; i < c; i += 256) {
        cu[i] = g_cu  [row * CAP + i];
        ci[i] = g_cidx[row * CAP + i];
    }
    __syncthreads();
    // exact rank: (key desc, index asc) matches jax.lax.top_k ordering & tie-break
    for (int i = threadIdx.x; i < c; i += 256) {
        unsigned int ui = cu[i];
        int idi = ci[i];
        int r = 0;
        for (int j = 0; j < c; j++) {
            unsigned int uj = cu[j];
            r += (uj > ui) || (uj == ui && ci[j] < idi);
        }
        if (r < 64) { selS[r] = funmono(ui); selI[r] = idi; }
    }
    __syncthreads();
    int kd = *pkd; if (kd > 64) kd = 64; if (kd < 1) kd = 1;
    if (kd > c) kd = c;
    if (threadIdx.x == 0) {
        float mx = selS[0];
        float sum = 0.f;
        for (int r = 0; r < kd; r++) { float e = expf(selS[r] - mx); w[r] = e; sum += e; }
        float inv = 1.0f / sum;
        for (int r = 0; r < kd; r++) w[r] *= inv;
    }
    __syncthreads();
    for (int d = threadIdx.x; d < 512; d += 256) {
        float acc = 0.f;
        for (int r = 0; r < kd; r++)
            acc += w[r] * pool_params[(size_t)selI[r] * 512 + d];
        out[row * 512 + d] = acc;
    }
}

// ---------------- launch ----------------
extern "C" void kernel_launch(void* const* d_in, const int* in_sizes, int n_in,
                              void* d_out, int out_size) {
    const float* hidden      = (const float*)d_in[0];
    const float* pool_params = (const float*)d_in[1];
    const float* pool_keys   = (const float*)d_in[2];
    const float* W           = (const float*)d_in[3];
    const float* bias        = (const float*)d_in[4];
    const int*   pkd         = (const int*)d_in[5];
    const int*   pmk         = (const int*)d_in[6];

    int B = out_size / 512;          if (B > MAXB) B = MAXB;
    int T = in_sizes[0] / (B * 512);
    int N = in_sizes[2] / 512;       if (N > MAXN) N = MAXN;

    k_zero<<<1, 1024>>>();
    k_mean<<<dim3(B, 8), 512>>>(hidden, T);
    k_query<<<B, 256>>>(W, bias, T);
    k_scores<<<(N + TN - 1) / TN, 256>>>(pool_keys, N);
    int gx = ((N >> 2) + F4PB - 1) / F4PB;
    k_hist<<<dim3(gx, B), 256>>>(N);
    k_thresh<<<B, 32>>>(pmk);
    k_collect<<<dim3(gx, B), 256>>>(N);
    k_final<<<B, 256>>>(pool_params, pkd, (float*)d_out, N);
}

// round 8
// speedup vs baseline: 1.0781x; 1.0781x over previous
#include <cuda_runtime.h>
#include <cuda_bf16.h>
#include <cstdint>

// ---------------- scratch (static __device__, no allocation) ----------------
#define MAXB 32
#define MAXN 500000
#define CAP  4096

__device__ float        g_pool8 [MAXB * 8 * 512];
__device__ float        g_queryT[512 * 32];              // [K-dim c][query b]
__device__ float        g_scores[(size_t)MAXB * MAXN];   // 64 MB
__device__ unsigned int g_rowmax[MAXB];
__device__ unsigned int g_hist16[MAXB * 16];
__device__ unsigned int g_thresh[MAXB];
__device__ int          g_ccount[MAXB];
__device__ unsigned int g_cu    [MAXB * CAP];
__device__ int          g_cidx  [MAXB * CAP];

__device__ __forceinline__ unsigned int fmono(float f) {
    unsigned int u = __float_as_uint(f);
    return (u & 0x80000000u) ? ~u : (u | 0x80000000u);
}
__device__ __forceinline__ float funmono(unsigned int u) {
    unsigned int o = (u & 0x80000000u) ? (u ^ 0x80000000u) : ~u;
    return __uint_as_float(o);
}

// packed fp32x2 FMA (FFMA2) — only reachable via PTX on sm_103a
__device__ __forceinline__ float2 ffma2(float2 a, float2 b, float2 c) {
    unsigned long long au = *reinterpret_cast<unsigned long long*>(&a);
    unsigned long long bu = *reinterpret_cast<unsigned long long*>(&b);
    unsigned long long cu = *reinterpret_cast<unsigned long long*>(&c);
    unsigned long long du;
    asm("fma.rn.f32x2 %0, %1, %2, %3;" : "=l"(du) : "l"(au), "l"(bu), "l"(cu));
    return *reinterpret_cast<float2*>(&du);
}

__device__ __forceinline__ void cp_async16(void* smem_dst, const void* gmem_src) {
    unsigned int d = (unsigned int)__cvta_generic_to_shared(smem_dst);
    asm volatile("cp.async.cg.shared.global [%0], [%1], 16;" :: "r"(d), "l"(gmem_src));
}

#define INV_SQRT_D 0.04419417382415922f   // 1/sqrt(512)

// ---------------- K0: zero small scratch ----------------
__global__ void k_zero() {
    int i = threadIdx.x;
    if (i < MAXB * 16) g_hist16[i] = 0u;
    if (i < MAXB) { g_ccount[i] = 0; g_rowmax[i] = 0u; }
}

// ---------------- K1: partial mean over T chunks ----------------
__global__ void k_mean(const float* __restrict__ hidden, int T) {
    int b  = blockIdx.x;
    int tc = blockIdx.y;              // 8 chunks
    int d  = threadIdx.x;             // 512 threads
    int rows_per = (T + 7) / 8;
    int t0 = tc * rows_per;
    int t1 = t0 + rows_per; if (t1 > T) t1 = T;
    const float* hp = hidden + ((size_t)b * T + t0) * 512 + d;
    float s0 = 0.f, s1 = 0.f, s2 = 0.f, s3 = 0.f;
    int nt = t1 - t0, t = 0;
    for (; t + 4 <= nt; t += 4) {
        s0 += hp[(size_t)(t + 0) * 512]; s1 += hp[(size_t)(t + 1) * 512];
        s2 += hp[(size_t)(t + 2) * 512]; s3 += hp[(size_t)(t + 3) * 512];
    }
    float s = (s0 + s1) + (s2 + s3);
    for (; t < nt; t++) s += hp[(size_t)t * 512];
    g_pool8[((size_t)b * 8 + tc) * 512 + d] = s;
}

// ---------------- K2: queryT[d][b] = (mean @ W + b)[d], high-MLP ----------------
__global__ void k_query(const float* __restrict__ W, const float* __restrict__ bias, int T) {
    __shared__ float p[512];
    int b = blockIdx.x, tid = threadIdx.x;          // 256 threads
    float invT = 1.0f / (float)T;
    for (int i = tid; i < 512; i += 256) {
        float s = 0.f;
#pragma unroll
        for (int tc = 0; tc < 8; tc++) s += g_pool8[((size_t)b * 8 + tc) * 512 + i];
        p[i] = s * invT;
    }
    __syncthreads();
    int d = tid * 2;
    float a0 = 0.f, a1 = 0.f;
#pragma unroll 16
    for (int k = 0; k < 512; k++) {
        float2 wv = *reinterpret_cast<const float2*>(W + (size_t)k * 512 + d);
        float pv = p[k];
        a0 += pv * wv.x; a1 += pv * wv.y;
    }
    g_queryT[(size_t)d * 32 + b]       = a0 + bias[d];
    g_queryT[(size_t)(d + 1) * 32 + b] = a1 + bias[d + 1];
}

// ---------------- K3: scores GEMM — query-paired FFMA2, 3 CTAs/SM ----------------
// Block tile: 256 keys x 32 queries, K-chunk 16, cp.async double-buffered.
// 256 threads = 8 warps: qg = w&3 (8-query group), kg = w>>2 (128-key half).
// Thread: 4 keys x 8 queries (4 query-pair float2 accs per key) -> 32 acc regs.
#define TN 256
#define KC 16
__global__ __launch_bounds__(256, 3) void k_scores(const float* __restrict__ keys, int N) {
    __shared__ float4 ks4[2][4][TN];    // [buf][c4-quad][row]  32 KB
    __shared__ float4 qt4[2][KC][8];    // [buf][c][q-quad]      4 KB
    int n0   = blockIdx.x * TN;
    int tid  = threadIdx.x;
    int lane = tid & 31;
    int w    = tid >> 5;
    int qg   = w & 3;          // query group: queries qg*8 .. qg*8+7
    int kg   = w >> 2;         // key half: rows [0,128) / [128,256)
    int krow = kg * 128 + lane;

    float2 acc[4][4];
#pragma unroll
    for (int i = 0; i < 4; i++)
#pragma unroll
        for (int j = 0; j < 4; j++) acc[i][j] = make_float2(0.f, 0.f);

    // ---- prefetch chunk 0 ----
    {
        const int c0 = 0;
#pragma unroll
        for (int it = 0; it < 4; it++) {
            int v = it * 256 + tid;      // 0..1023 = 256 rows x 4 float4
            int row = v >> 2, c4 = v & 3;
            int n = n0 + row; if (n >= N) n = N - 1;
            cp_async16(&ks4[0][c4][row], keys + (size_t)n * 512 + c0 + c4 * 4);
        }
        if (tid < 128) {                 // KC(16) x 8 = 128 float4s
            int cl = tid >> 3, j4 = tid & 7;         // cl 0..15, j4 0..7
            cp_async16(&qt4[0][cl][j4], g_queryT + (size_t)(c0 + cl) * 32 + j4 * 4);
        }
        asm volatile("cp.async.commit_group;");
    }

    const int NCH = 512 / KC;   // 32
    for (int ch = 0; ch < NCH; ch++) {
        int buf = ch & 1;
        if (ch + 1 < NCH) {
            int c0 = (ch + 1) * KC;
            int nb = (ch + 1) & 1;
#pragma unroll
            for (int it = 0; it < 4; it++) {
                int v = it * 256 + tid;
                int row = v >> 2, c4 = v & 3;
                int n = n0 + row; if (n >= N) n = N - 1;
                cp_async16(&ks4[nb][c4][row], keys + (size_t)n * 512 + c0 + c4 * 4);
            }
            if (tid < 128) {
                int cl = tid >> 3, j4 = tid & 7;
                cp_async16(&qt4[nb][cl][j4], g_queryT + (size_t)(c0 + cl) * 32 + j4 * 4);
            }
            asm volatile("cp.async.commit_group;");
            asm volatile("cp.async.wait_group 1;");
        } else {
            asm volatile("cp.async.wait_group 0;");
        }
        __syncthreads();

#pragma unroll
        for (int c4 = 0; c4 < 4; c4++) {
            float4 kv[4];
#pragma unroll
            for (int i = 0; i < 4; i++) kv[i] = ks4[buf][c4][krow + 32 * i];
#pragma unroll
            for (int e = 0; e < 4; e++) {
                // 8 queries for this K-step = 2 float4 broadcasts
                float4 qa = qt4[buf][c4 * 4 + e][qg * 2];
                float4 qb = qt4[buf][c4 * 4 + e][qg * 2 + 1];
#pragma unroll
                for (int i = 0; i < 4; i++) {
                    float ke = (e == 0) ? kv[i].x : (e == 1) ? kv[i].y
                             : (e == 2) ? kv[i].z : kv[i].w;
                    float2 kb = make_float2(ke, ke);
                    acc[i][0] = ffma2(kb, make_float2(qa.x, qa.y), acc[i][0]);
                    acc[i][1] = ffma2(kb, make_float2(qa.z, qa.w), acc[i][1]);
                    acc[i][2] = ffma2(kb, make_float2(qb.x, qb.y), acc[i][2]);
                    acc[i][3] = ffma2(kb, make_float2(qb.z, qb.w), acc[i][3]);
                }
            }
        }
        __syncthreads();
    }

    // epilogue: scores + per-row running max
#pragma unroll
    for (int j = 0; j < 4; j++) {
        int m0 = qg * 8 + j * 2;
        unsigned int umx = 0u, umy = 0u;
#pragma unroll
        for (int i = 0; i < 4; i++) {
            int n = n0 + krow + 32 * i;
            if (n < N) {
                float sx = acc[i][j].x * INV_SQRT_D;
                float sy = acc[i][j].y * INV_SQRT_D;
                g_scores[(size_t)m0 * N + n]       = sx;
                g_scores[(size_t)(m0 + 1) * N + n] = sy;
                unsigned int ux = fmono(sx), uy = fmono(sy);
                if (ux > umx) umx = ux;
                if (uy > umy) umy = uy;
            }
        }
        umx = __reduce_max_sync(0xffffffffu, umx);
        umy = __reduce_max_sync(0xffffffffu, umy);
        if (lane == 0) {
            atomicMax(&g_rowmax[m0], umx);
            atomicMax(&g_rowmax[m0 + 1], umy);
        }
    }
}

// ---------------- K4: 16-bin hist restricted to top bins below rowmax ----------------
#define F4PB 8192   // float4s per block
__global__ void k_hist(int N) {
    __shared__ unsigned int h[16];
    int row = blockIdx.y;
    int N4  = N >> 2;
    if (threadIdx.x < 16) h[threadIdx.x] = 0u;
    __syncthreads();
    int lo = (int)(g_rowmax[row] >> 20) - 15;
    const float4* sr = reinterpret_cast<const float4*>(g_scores + (size_t)row * N);
    int base = blockIdx.x * F4PB;
    for (int i = threadIdx.x; i < F4PB; i += 256) {
        int i4 = base + i;
        if (i4 < N4) {
            float4 v = sr[i4];
            int b0 = (int)(fmono(v.x) >> 20) - lo;
            int b1 = (int)(fmono(v.y) >> 20) - lo;
            int b2 = (int)(fmono(v.z) >> 20) - lo;
            int b3 = (int)(fmono(v.w) >> 20) - lo;
            if (b0 >= 0) atomicAdd(&h[b0], 1u);
            if (b1 >= 0) atomicAdd(&h[b1], 1u);
            if (b2 >= 0) atomicAdd(&h[b2], 1u);
            if (b3 >= 0) atomicAdd(&h[b3], 1u);
        }
    }
    if (blockIdx.x == 0) {
        for (int idx = N4 * 4 + (int)threadIdx.x; idx < N; idx += 256) {
            int b = (int)(fmono(g_scores[(size_t)row * N + idx]) >> 20) - lo;
            if (b >= 0) atomicAdd(&h[b], 1u);
        }
    }
    __syncthreads();
    if (threadIdx.x < 16 && h[threadIdx.x])
        atomicAdd(&g_hist16[row * 16 + threadIdx.x], h[threadIdx.x]);
}

// ---------------- K5: pick threshold bin (cum from top >= max_k) ----------------
__global__ void k_thresh(const int* __restrict__ pmk) {
    int row = blockIdx.x;
    if (threadIdx.x == 0) {
        int lo = (int)(g_rowmax[row] >> 20) - 15;
        int mk = *pmk; if (mk < 1) mk = 1; if (mk > CAP) mk = CAP;
        unsigned int cum = 0;
        int tb = lo;   // fallback: everything in range
        for (int b = 15; b >= 0; b--) {
            cum += g_hist16[row * 16 + b];
            if (cum >= (unsigned int)mk) { tb = lo + b; break; }
        }
        g_thresh[row] = (unsigned int)tb;
    }
}

// ---------------- K6: collect candidates with bin >= threshold ----------------
__global__ void k_collect(int N) {
    int row = blockIdx.y;
    int N4  = N >> 2;
    unsigned int tb = g_thresh[row];
    const float4* sr = reinterpret_cast<const float4*>(g_scores + (size_t)row * N);
    int base = blockIdx.x * F4PB;
    for (int i = threadIdx.x; i < F4PB; i += 256) {
        int i4 = base + i;
        if (i4 < N4) {
            float4 v = sr[i4];
            unsigned int u[4] = {fmono(v.x), fmono(v.y), fmono(v.z), fmono(v.w)};
#pragma unroll
            for (int e = 0; e < 4; e++) {
                if ((u[e] >> 20) >= tb) {
                    int pos = atomicAdd(&g_ccount[row], 1);
                    if (pos < CAP) {
                        g_cu  [row * CAP + pos] = u[e];
                        g_cidx[row * CAP + pos] = i4 * 4 + e;
                    }
                }
            }
        }
    }
    if (blockIdx.x == 0) {
        for (int idx = N4 * 4 + (int)threadIdx.x; idx < N; idx += 256) {
            unsigned int u = fmono(g_scores[(size_t)row * N + idx]);
            if ((u >> 20) >= tb) {
                int pos = atomicAdd(&g_ccount[row], 1);
                if (pos < CAP) {
                    g_cu  [row * CAP + pos] = u;
                    g_cidx[row * CAP + pos] = idx;
                }
            }
        }
    }
}

// ---------------- K7: exact rank, softmax(k_dyn), gather + aggregate ----------------
__global__ void k_final(const float* __restrict__ pool_params, const int* __restrict__ pkd,
                        float* __restrict__ out, int N) {
    __shared__ unsigned int cu[CAP];
    __shared__ int          ci[CAP];
    __shared__ float        selS[64];
    __shared__ int          selI[64];
    __shared__ float        w[64];
    int row = blockIdx.x;
    int c   = g_ccount[row]; if (c > CAP) c = CAP;
    for (int i = threadIdx.x; i < c; i += 256) {
        cu[i] = g_cu  [row * CAP + i];
        ci[i] = g_cidx[row * CAP + i];
    }
    __syncthreads();
    // exact rank: (key desc, index asc) matches jax.lax.top_k ordering & tie-break
    for (int i = threadIdx.x; i < c; i += 256) {
        unsigned int ui = cu[i];
        int idi = ci[i];
        int r = 0;
        for (int j = 0; j < c; j++) {
            unsigned int uj = cu[j];
            r += (uj > ui) || (uj == ui && ci[j] < idi);
        }
        if (r < 64) { selS[r] = funmono(ui); selI[r] = idi; }
    }
    __syncthreads();
    int kd = *pkd; if (kd > 64) kd = 64; if (kd < 1) kd = 1;
    if (kd > c) kd = c;
    if (threadIdx.x == 0) {
        float mx = selS[0];
        float sum = 0.f;
        for (int r = 0; r < kd; r++) { float e = expf(selS[r] - mx); w[r] = e; sum += e; }
        float inv = 1.0f / sum;
        for (int r = 0; r < kd; r++) w[r] *= inv;
    }
    __syncthreads();
    for (int d = threadIdx.x; d < 512; d += 256) {
        float acc = 0.f;
        for (int r = 0; r < kd; r++)
            acc += w[r] * pool_params[(size_t)selI[r] * 512 + d];
        out[row * 512 + d] = acc;
    }
}

// ---------------- launch ----------------
extern "C" void kernel_launch(void* const* d_in, const int* in_sizes, int n_in,
                              void* d_out, int out_size) {
    const float* hidden      = (const float*)d_in[0];
    const float* pool_params = (const float*)d_in[1];
    const float* pool_keys   = (const float*)d_in[2];
    const float* W           = (const float*)d_in[3];
    const float* bias        = (const float*)d_in[4];
    const int*   pkd         = (const int*)d_in[5];
    const int*   pmk         = (const int*)d_in[6];

    int B = out_size / 512;          if (B > MAXB) B = MAXB;
    int T = in_sizes[0] / (B * 512);
    int N = in_sizes[2] / 512;       if (N > MAXN) N = MAXN;

    k_zero<<<1, 1024>>>();
    k_mean<<<dim3(B, 8), 512>>>(hidden, T);
    k_query<<<B, 256>>>(W, bias, T);
    k_scores<<<(N + TN - 1) / TN, 256>>>(pool_keys, N);
    int gx = ((N >> 2) + F4PB - 1) / F4PB;
    k_hist<<<dim3(gx, B), 256>>>(N);
    k_thresh<<<B, 32>>>(pmk);
    k_collect<<<dim3(gx, B), 256>>>(N);
    k_final<<<B, 256>>>(pool_params, pkd, (float*)d_out, N);
}